// round 12
// baseline (speedup 1.0000x reference)
#include <cuda_runtime.h>
#include <cuda_bf16.h>
#include <cuda_fp16.h>
#include <math.h>
#include <stdint.h>

// Problem constants
#define BB 4
#define LL 2048
#define DD 512
#define HH 8
#define DKK 64
#define UU 24
#define BH (BB*HH)
#define MTOT (BB*LL)     // 8192 rows per GEMM

// ---------------- scratch (device globals; no allocation allowed) ----------
// q/k/v/ctx all row-major: row = b*LL + l, col = h*DKK + dk
__device__ float g_q[MTOT*DD];
__device__ float g_k[MTOT*DD];
__device__ float g_v[MTOT*DD];
__device__ float g_m[BB*HH*LL];
__device__ int   g_top[BB*HH*UU];
__device__ float g_ctx[MTOT*DD];

// pre-split transposed weights W^T[n][k]: bf16 hi/lo for Wq,Wk; fp16 for Wv,Wo
__device__ __nv_bfloat16 g_wh[2][DD*DD];
__device__ __nv_bfloat16 g_wl[2][DD*DD];
__device__ __half        g_wf[2][DD*DD];

// cumsum scratch
__device__ float g_segsum[BH][16][4][DKK];
__device__ float g_chpre[BH][16][DKK];

// topk scratch
__device__ float g_cand_v[BH][8][UU];
__device__ int   g_cand_i[BH][8][UU];

// =========================== helpers =======================================
__device__ __forceinline__ uint32_t smem_u32(const void* p) {
    uint32_t a;
    asm("{ .reg .u64 t; cvta.to.shared.u64 t, %1; cvt.u32.u64 %0, t; }"
        : "=r"(a) : "l"(p));
    return a;
}
__device__ __forceinline__ void cpasync16(uint32_t saddr, const void* gptr) {
    asm volatile("cp.async.cg.shared.global [%0], [%1], 16;"
                 :: "r"(saddr), "l"(__cvta_generic_to_global(gptr)) : "memory");
}
__device__ __forceinline__ void cp_commit() {
    asm volatile("cp.async.commit_group;" ::: "memory");
}
template<int N>
__device__ __forceinline__ void cp_wait() {
    asm volatile("cp.async.wait_group %0;" :: "n"(N) : "memory");
}
template<int F16>
__device__ __forceinline__ void mma_any(float& c0, float& c1, float& c2, float& c3,
                                        uint32_t a0, uint32_t a1, uint32_t a2, uint32_t a3,
                                        uint32_t b0, uint32_t b1) {
    if (F16)
        asm volatile("mma.sync.aligned.m16n8k16.row.col.f32.f16.f16.f32 "
                     "{%0,%1,%2,%3}, {%4,%5,%6,%7}, {%8,%9}, {%0,%1,%2,%3};"
                     : "+f"(c0), "+f"(c1), "+f"(c2), "+f"(c3)
                     : "r"(a0), "r"(a1), "r"(a2), "r"(a3), "r"(b0), "r"(b1));
    else
        asm volatile("mma.sync.aligned.m16n8k16.row.col.f32.bf16.bf16.f32 "
                     "{%0,%1,%2,%3}, {%4,%5,%6,%7}, {%8,%9}, {%0,%1,%2,%3};"
                     : "+f"(c0), "+f"(c1), "+f"(c2), "+f"(c3)
                     : "r"(a0), "r"(a1), "r"(a2), "r"(a3), "r"(b0), "r"(b1));
}
__device__ __forceinline__ void ldsm4(uint32_t& r0, uint32_t& r1, uint32_t& r2, uint32_t& r3,
                                      uint32_t addr) {
    asm volatile("ldmatrix.sync.aligned.m8n8.x4.shared.b16 {%0,%1,%2,%3}, [%4];"
                 : "=r"(r0), "=r"(r1), "=r"(r2), "=r"(r3) : "r"(addr));
}
__device__ __forceinline__ void split2(float x, __nv_bfloat16& h, __nv_bfloat16& l) {
    h = __float2bfloat16_rn(x);
    l = __float2bfloat16_rn(x - __bfloat162float(h));
}
__device__ __forceinline__ uint32_t pack2(__nv_bfloat16 a, __nv_bfloat16 b) {
    return (uint32_t)__bfloat16_as_ushort(a) | ((uint32_t)__bfloat16_as_ushort(b) << 16);
}
__device__ __forceinline__ void split2h(float x, __half& h, __half& l) {
    h = __float2half_rn(x);
    l = __float2half_rn(x - __half2float(h));
}
__device__ __forceinline__ uint32_t pack2h(__half a, __half b) {
    return (uint32_t)__half_as_ushort(a) | ((uint32_t)__half_as_ushort(b) << 16);
}

// W[k][n] -> W^T[n][k]: bf16 hi/lo (z=0,1: Wq,Wk), fp16 (z=2,3: Wv,Wo)
__global__ __launch_bounds__(256) void transpose_split_kernel(const float* __restrict__ Wq,
                                                              const float* __restrict__ Wk,
                                                              const float* __restrict__ Wv,
                                                              const float* __restrict__ Wo)
{
    __shared__ float tile[32][33];
    const int z = blockIdx.z;
    const float* W = (z == 0) ? Wq : (z == 1) ? Wk : (z == 2) ? Wv : Wo;
    const int k0 = blockIdx.y * 32, n0 = blockIdx.x * 32;
#pragma unroll
    for (int r = 0; r < 32; r += 8)
        tile[threadIdx.y + r][threadIdx.x] = W[(size_t)(k0 + threadIdx.y + r) * DD + n0 + threadIdx.x];
    __syncthreads();
#pragma unroll
    for (int r = 0; r < 32; r += 8) {
        const int n = n0 + threadIdx.y + r, k = k0 + threadIdx.x;
        const float w = tile[threadIdx.x][threadIdx.y + r];
        if (z < 2) {
            __nv_bfloat16 h, l;
            split2(w, h, l);
            g_wh[z][(size_t)n * DD + k] = h;
            g_wl[z][(size_t)n * DD + k] = l;
        } else {
            g_wf[z - 2][(size_t)n * DD + k] = __float2half_rn(w);
        }
    }
}

// ====== HMMA GEMM: 128x128 tile, BK=32, 2-stage, 1 sync/chunk, occ=2 =======
#define STG 40
#define ARRB (128*STG*2)
#define OFF_AH 0
#define OFF_AL (ARRB)
#define OFF_BH (2*ARRB)
#define OFF_BL (3*ARRB)
#define STAGE_B (4*ARRB)                // 40960
#define GSMEM (2*STAGE_B)               // 81920 -> 2 CTAs/SM

template<int F16>
__device__ __forceinline__ void split_sts(char* stagebase, int lrow, int lhalf,
                                          const float4* v4)
{
    uint16_t* ah = (uint16_t*)(stagebase + OFF_AH);
    uint16_t* al = (uint16_t*)(stagebase + OFF_AL);
#pragma unroll
    for (int qq = 0; qq < 4; qq++) {
        const float4 v = v4[qq];
        uint2 uh, ul;
        if (F16) {
            __half h0, h1, h2, h3, l0, l1, l2, l3;
            split2h(v.x, h0, l0); split2h(v.y, h1, l1);
            split2h(v.z, h2, l2); split2h(v.w, h3, l3);
            uh.x = pack2h(h0, h1); uh.y = pack2h(h2, h3);
            ul.x = pack2h(l0, l1); ul.y = pack2h(l2, l3);
        } else {
            __nv_bfloat16 h0, h1, h2, h3, l0, l1, l2, l3;
            split2(v.x, h0, l0); split2(v.y, h1, l1);
            split2(v.z, h2, l2); split2(v.w, h3, l3);
            uh.x = pack2(h0, h1); uh.y = pack2(h2, h3);
            ul.x = pack2(l0, l1); ul.y = pack2(l2, l3);
        }
        *(uint2*)(ah + lrow * STG + lhalf + qq * 4) = uh;
        *(uint2*)(al + lrow * STG + lhalf + qq * 4) = ul;
    }
}

template<int F16>
__device__ __forceinline__ void load_B(uint32_t s, const uint16_t* __restrict__ Bh,
                                       const uint16_t* __restrict__ Bl,
                                       int n0, int k0, int tid)
{
#pragma unroll
    for (int rep = 0; rep < 2; rep++) {
        const int c = tid + rep * 256;
        const int row = c >> 2, kp = (c & 3) * 8;
        cpasync16(s + OFF_BH + (uint32_t)(row * STG + kp) * 2,
                  Bh + (size_t)(n0 + row) * DD + k0 + kp);
    }
    if (!F16) {
#pragma unroll
        for (int rep = 0; rep < 2; rep++) {
            const int c = tid + rep * 256;
            const int row = c >> 2, kp = (c & 3) * 8;
            cpasync16(s + OFF_BL + (uint32_t)(row * STG + kp) * 2,
                      Bl + (size_t)(n0 + row) * DD + k0 + kp);
        }
    }
    cp_commit();
}

template<int F16>
__device__ __forceinline__ void gemm_core(const float* __restrict__ A,
                                          const uint16_t* __restrict__ Bh,
                                          const uint16_t* __restrict__ Bl,
                                          const float* __restrict__ bias,
                                          float* __restrict__ dst, char* smraw,
                                          int m0, int n0)
{
    const int tid = threadIdx.x;
    const uint32_t sbase = smem_u32(smraw);

    const int wid = tid >> 5, lane = tid & 31;
    const int wm = (wid >> 2) * 64;
    const int wn = (wid & 3) * 32;
    const int g  = lane >> 2;
    const int q2 = (lane & 3) * 2;

    const int aRow = wm + (lane & 7) + ((lane >> 3) & 1) * 8;
    const int aColE = (lane >> 4) * 8;
    const int bRow = wn + (lane & 7) + ((lane >> 4) & 1) * 8;
    const int bColE = ((lane >> 3) & 1) * 8;

    const int lrow = tid >> 1, lhalf = (tid & 1) * 16;
    const float* Arow = A + (size_t)(m0 + lrow) * DD + lhalf;

    float acc[4][4][4];
#pragma unroll
    for (int i = 0; i < 4; i++)
#pragma unroll
        for (int j = 0; j < 4; j++)
#pragma unroll
            for (int r = 0; r < 4; r++) acc[i][j][r] = 0.f;

    float4 areg[4];

#pragma unroll
    for (int qq = 0; qq < 4; qq++) areg[qq] = *(const float4*)(Arow + qq * 4);
    split_sts<F16>(smraw, lrow, lhalf, areg);
    load_B<F16>(sbase, Bh, Bl, n0, 0, tid);

    for (int c = 0; c < 16; c++) {
        cp_wait<0>();
        __syncthreads();

        if (c < 15) {
            const int k1 = (c + 1) * 32;
#pragma unroll
            for (int qq = 0; qq < 4; qq++)
                areg[qq] = *(const float4*)(Arow + k1 + qq * 4);
            load_B<F16>(sbase + (uint32_t)((c + 1) & 1) * STAGE_B, Bh, Bl, n0, k1, tid);
        }

        const uint32_t stb = sbase + (uint32_t)(c & 1) * STAGE_B;
        const uint32_t aH = stb + OFF_AH + (uint32_t)(aRow * STG + aColE) * 2;
        const uint32_t aL = stb + OFF_AL + (uint32_t)(aRow * STG + aColE) * 2;
        const uint32_t bH = stb + OFF_BH + (uint32_t)(bRow * STG + bColE) * 2;
        const uint32_t bL = stb + OFF_BL + (uint32_t)(bRow * STG + bColE) * 2;

#pragma unroll
        for (int ks = 0; ks < 32; ks += 16) {
            uint32_t ah4[4][4], al4[4][4], bh4[2][4], bl4[2][4];
#pragma unroll
            for (int i = 0; i < 4; i++)
                ldsm4(ah4[i][0], ah4[i][1], ah4[i][2], ah4[i][3],
                      aH + (uint32_t)(i * 16 * STG + ks) * 2);
#pragma unroll
            for (int jp = 0; jp < 2; jp++)
                ldsm4(bh4[jp][0], bh4[jp][1], bh4[jp][2], bh4[jp][3],
                      bH + (uint32_t)(jp * 16 * STG + ks) * 2);
            if (!F16) {
#pragma unroll
                for (int jp = 0; jp < 2; jp++)
                    ldsm4(bl4[jp][0], bl4[jp][1], bl4[jp][2], bl4[jp][3],
                          bL + (uint32_t)(jp * 16 * STG + ks) * 2);
            }
#pragma unroll
            for (int i = 0; i < 4; i++)
                ldsm4(al4[i][0], al4[i][1], al4[i][2], al4[i][3],
                      aL + (uint32_t)(i * 16 * STG + ks) * 2);

#pragma unroll
            for (int i = 0; i < 4; i++)
#pragma unroll
                for (int j = 0; j < 4; j++) {
                    const int jp = j >> 1, jo = (j & 1) * 2;
                    mma_any<F16>(acc[i][j][0], acc[i][j][1], acc[i][j][2], acc[i][j][3],
                                 ah4[i][0], ah4[i][1], ah4[i][2], ah4[i][3],
                                 bh4[jp][jo], bh4[jp][jo + 1]);
                }
            if (!F16) {
#pragma unroll
                for (int i = 0; i < 4; i++)
#pragma unroll
                    for (int j = 0; j < 4; j++) {
                        const int jp = j >> 1, jo = (j & 1) * 2;
                        mma_any<F16>(acc[i][j][0], acc[i][j][1], acc[i][j][2], acc[i][j][3],
                                     ah4[i][0], ah4[i][1], ah4[i][2], ah4[i][3],
                                     bl4[jp][jo], bl4[jp][jo + 1]);
                    }
            }
#pragma unroll
            for (int i = 0; i < 4; i++)
#pragma unroll
                for (int j = 0; j < 4; j++) {
                    const int jp = j >> 1, jo = (j & 1) * 2;
                    mma_any<F16>(acc[i][j][0], acc[i][j][1], acc[i][j][2], acc[i][j][3],
                                 al4[i][0], al4[i][1], al4[i][2], al4[i][3],
                                 bh4[jp][jo], bh4[jp][jo + 1]);
                }
        }

        if (c < 15)
            split_sts<F16>(smraw + ((c + 1) & 1) * STAGE_B, lrow, lhalf, areg);
    }

    // epilogue: plain row-major store
#pragma unroll
    for (int i = 0; i < 4; i++) {
#pragma unroll
        for (int j = 0; j < 4; j++) {
            const int gm0 = m0 + wm + i * 16 + g;
            const int gn  = n0 + wn + j * 8 + q2;
            const float b0 = bias[gn], b1 = bias[gn + 1];
            float* p0 = dst + (size_t)gm0 * DD + gn;
            p0[0] = acc[i][j][0] + b0; p0[1] = acc[i][j][1] + b1;
            float* p1 = dst + (size_t)(gm0 + 8) * DD + gn;
            p1[0] = acc[i][j][2] + b0; p1[1] = acc[i][j][3] + b1;
        }
    }
}

// merged Q/K/V projections: z=0,1 -> bf16 3-term; z=2 -> fp16 2-term
__global__ __launch_bounds__(256, 2) void hgemm_qkv(const float* __restrict__ q,
                                                    const float* __restrict__ k,
                                                    const float* __restrict__ v,
                                                    const float* __restrict__ bq,
                                                    const float* __restrict__ bk,
                                                    const float* __restrict__ bv)
{
    extern __shared__ char smraw[];
    const int z = blockIdx.z;
    const int m0 = blockIdx.y * 128, n0 = blockIdx.x * 128;
    if (z < 2) {
        gemm_core<0>((z == 0) ? q : k,
                     (const uint16_t*)g_wh[z], (const uint16_t*)g_wl[z],
                     (z == 0) ? bq : bk, (z == 0) ? g_q : g_k, smraw, m0, n0);
    } else {
        gemm_core<1>(v, (const uint16_t*)g_wf[0], (const uint16_t*)g_wf[0],
                     bv, g_v, smraw, m0, n0);
    }
}

__global__ __launch_bounds__(256, 2) void hgemm_out(const float* __restrict__ bo,
                                                    float* __restrict__ outp)
{
    extern __shared__ char smraw[];
    gemm_core<1>((const float*)g_ctx, (const uint16_t*)g_wf[1], (const uint16_t*)g_wf[1],
                 bo, outp, smraw, blockIdx.y * 128, blockIdx.x * 128);
}

// =========================== non-GEMM kernels ==============================
__global__ __launch_bounds__(256) void probe_kernel(const int* __restrict__ idx)
{
    const int w = (blockIdx.x * blockDim.x + threadIdx.x) >> 5;
    const int lane = threadIdx.x & 31;
    if (w >= BB * HH * LL) return;
    const int l = w & (LL - 1);
    const int bh = w >> 11;
    const int b = bh >> 3, h = bh & 7;

    const float* qrow = g_q + (size_t)(b * LL + l) * DD + h * DKK;
    const float2 qv = *(const float2*)(qrow + lane * 2);
    const float* kbase = g_k + (size_t)b * LL * DD + h * DKK;
    const int* ip = idx + l * UU;
    const int myidx = (lane < UU) ? ip[lane] : 0;

    float mx = -INFINITY, sm = 0.f;
#pragma unroll 4
    for (int s = 0; s < UU; s++) {
        const int j = __shfl_sync(0xffffffffu, myidx, s);
        const float2 kk = *(const float2*)(kbase + (size_t)j * DD + lane * 2);
        float p = qv.x * kk.x + qv.y * kk.y;
#pragma unroll
        for (int o = 16; o > 0; o >>= 1) p += __shfl_xor_sync(0xffffffffu, p, o);
        mx = fmaxf(mx, p);
        sm += p;
    }
    if (lane == 0) g_m[w] = mx - sm * (1.0f / LL);
}

// topk phase 1: block (bh, chunk of 256) -> local top-24 candidates
__global__ __launch_bounds__(256) void topk_p1()
{
    __shared__ float swv[8];
    __shared__ int   swi[8];
    __shared__ int   swin;
    const int bh = blockIdx.x, ch = blockIdx.y;
    const int t = threadIdx.x;
    const int wid = t >> 5, lane = t & 31;

    float v = g_m[(size_t)bh * LL + ch * 256 + t];

    for (int iter = 0; iter < UU; iter++) {
        float bv = v; int bi = t;
#pragma unroll
        for (int o = 16; o > 0; o >>= 1) {
            const float ov = __shfl_xor_sync(0xffffffffu, bv, o);
            const int   oi = __shfl_xor_sync(0xffffffffu, bi, o);
            if (ov > bv || (ov == bv && oi < bi)) { bv = ov; bi = oi; }
        }
        if (lane == 0) { swv[wid] = bv; swi[wid] = bi; }
        __syncthreads();
        if (t == 0) {
            float mv = swv[0]; int mi = swi[0];
#pragma unroll
            for (int w = 1; w < 8; w++)
                if (swv[w] > mv || (swv[w] == mv && swi[w] < mi)) { mv = swv[w]; mi = swi[w]; }
            g_cand_v[bh][ch][iter] = mv;
            g_cand_i[bh][ch][iter] = ch * 256 + mi;
            swin = mi;
        }
        __syncthreads();
        if (swin == t) v = -INFINITY;
    }
}

// topk phase 2: merge 8x24 candidates -> global top-24 (tie: smaller index)
__global__ __launch_bounds__(192) void topk_p2()
{
    __shared__ float swv[6];
    __shared__ int   swi[6];
    __shared__ int   swin;
    const int bh = blockIdx.x;
    const int t = threadIdx.x;          // 192 = 8*24
    const int wid = t >> 5, lane = t & 31;

    float v = g_cand_v[bh][t / UU][t % UU];
    int   gi = g_cand_i[bh][t / UU][t % UU];

    for (int iter = 0; iter < UU; iter++) {
        float bv = v; int bgi = gi; int bt = t;
#pragma unroll
        for (int o = 16; o > 0; o >>= 1) {
            const float ov = __shfl_xor_sync(0xffffffffu, bv, o);
            const int   ogi = __shfl_xor_sync(0xffffffffu, bgi, o);
            const int   ot = __shfl_xor_sync(0xffffffffu, bt, o);
            if (ov > bv || (ov == bv && ogi < bgi)) { bv = ov; bgi = ogi; bt = ot; }
        }
        if (lane == 0) { swv[wid] = bv; swi[wid] = (bgi << 8) | 0; }
        // pack: need both gi and local t; store separately
        __syncthreads();
        // serial merge by thread 0 using shuffle results stored per warp
        if (lane == 0) swi[wid] = bt;   // local winner thread
        __syncthreads();
        if (t == 0) {
            float mv = swv[0]; int mt = swi[0];
#pragma unroll
            for (int w = 1; w < 6; w++) {
                // compare using candidate values and global indices
                // fetch global idx of each warp winner from its thread via smem:
                // swv holds value; tiebreak needs gi -> recompute via g_cand arrays
                if (swv[w] > mv) { mv = swv[w]; mt = swi[w]; }
                else if (swv[w] == mv) {
                    const int gi_w = g_cand_i[bh][swi[w] / UU][swi[w] % UU];
                    const int gi_m = g_cand_i[bh][mt / UU][mt % UU];
                    if (gi_w < gi_m) { mv = swv[w]; mt = swi[w]; }
                }
            }
            g_top[bh * UU + iter] = g_cand_i[bh][mt / UU][mt % UU];
            swin = mt;
        }
        __syncthreads();
        if (swin == t) v = -INFINITY;
    }
}

// Batched sparse attention; writes results DIRECTLY into g_ctx (over cumsum)
#define QG 4
__global__ __launch_bounds__(256) void attn_kernel()
{
    __shared__ float qs[QG][DKK];
    __shared__ float sc[QG][LL];
    __shared__ float red[256];
    __shared__ int   pos_s[QG];

    const int bh = blockIdx.x / (UU / QG);
    const int grp = blockIdx.x % (UU / QG);
    const int t = threadIdx.x;
    const int wid = t >> 5, lane = t & 31;
    const int b = bh >> 3, h = bh & 7;

    const float* kb = g_k + (size_t)b * LL * DD + h * DKK;
    const float* vb = g_v + (size_t)b * LL * DD + h * DKK;

    {
        const int u = t >> 6, d = t & 63;
        const int p = g_top[bh * UU + grp * QG + u];
        if (d == 0) pos_s[u] = p;
        qs[u][d] = g_q[(size_t)(b * LL + p) * DD + h * DKK + d];
    }
    __syncthreads();

    const float scale = rsqrtf((float)DD);

    float lmax[QG];
#pragma unroll
    for (int u = 0; u < QG; u++) lmax[u] = -INFINITY;

    for (int j = t; j < LL; j += 256) {
        const float* kr = kb + (size_t)j * DD;
        float dot[QG];
#pragma unroll
        for (int u = 0; u < QG; u++) dot[u] = 0.f;
#pragma unroll
        for (int d4 = 0; d4 < 16; d4++) {
            float4 kk = *(const float4*)(kr + d4 * 4);
#pragma unroll
            for (int u = 0; u < QG; u++) {
                dot[u] += qs[u][d4 * 4] * kk.x + qs[u][d4 * 4 + 1] * kk.y +
                          qs[u][d4 * 4 + 2] * kk.z + qs[u][d4 * 4 + 3] * kk.w;
            }
        }
#pragma unroll
        for (int u = 0; u < QG; u++) {
            const float s = (j > pos_s[u]) ? -INFINITY : dot[u] * scale;
            sc[u][j] = s;
            lmax[u] = fmaxf(lmax[u], s);
        }
    }
#pragma unroll
    for (int u = 0; u < QG; u++) {
        float m = lmax[u];
#pragma unroll
        for (int o = 16; o > 0; o >>= 1) m = fmaxf(m, __shfl_xor_sync(0xffffffffu, m, o));
        if (lane == 0) red[u * 8 + wid] = m;
    }
    __syncthreads();
    float mx[QG];
#pragma unroll
    for (int u = 0; u < QG; u++) {
        float m = -INFINITY;
#pragma unroll
        for (int w = 0; w < 8; w++) m = fmaxf(m, red[u * 8 + w]);
        mx[u] = m;
    }
    __syncthreads();

    float lsum[QG];
#pragma unroll
    for (int u = 0; u < QG; u++) lsum[u] = 0.f;
    for (int j = t; j < LL; j += 256) {
#pragma unroll
        for (int u = 0; u < QG; u++) {
            const float p = __expf(sc[u][j] - mx[u]);
            sc[u][j] = p;
            lsum[u] += p;
        }
    }
#pragma unroll
    for (int u = 0; u < QG; u++) {
        float s = lsum[u];
#pragma unroll
        for (int o = 16; o > 0; o >>= 1) s += __shfl_xor_sync(0xffffffffu, s, o);
        if (lane == 0) red[u * 8 + wid] = s;
    }
    __syncthreads();
    float inv[QG];
#pragma unroll
    for (int u = 0; u < QG; u++) {
        float s = 0.f;
#pragma unroll
        for (int w = 0; w < 8; w++) s += red[u * 8 + w];
        inv[u] = 1.0f / s;
    }
    __syncthreads();

    const int d = t & 63, g4 = t >> 6;
    float acc[QG];
#pragma unroll
    for (int u = 0; u < QG; u++) acc[u] = 0.f;
    const int j0 = g4 * (LL / 4), j1 = j0 + (LL / 4);
    for (int j = j0; j < j1; j++) {
        const float v = vb[(size_t)j * DD + d];
#pragma unroll
        for (int u = 0; u < QG; u++) acc[u] += sc[u][j] * v;
    }
#pragma unroll
    for (int u = 0; u < QG; u++) {
        red[t] = acc[u];
        __syncthreads();
        if (t < DKK) {
            const float o = (red[t] + red[t + 64] + red[t + 128] + red[t + 192]) * inv[u];
            g_ctx[(size_t)(b * LL + pos_s[u]) * DD + h * DKK + t] = o;
        }
        __syncthreads();
    }
}

// ---- cumsum, 3-phase (row-major v -> row-major ctx) -----------------------
__global__ __launch_bounds__(256) void cumsum_p1()
{
    const int bh = blockIdx.x, ch = blockIdx.y;
    const int b = bh >> 3, h = bh & 7;
    const int t = threadIdx.x;
    const int d = t & 63, seg = t >> 6;
    const float* vb = g_v + (size_t)b * LL * DD + h * DKK;
    const int l0 = ch * 128 + seg * 32;
    float s = 0.f;
#pragma unroll 4
    for (int l = l0; l < l0 + 32; l++) s += vb[(size_t)l * DD + d];
    g_segsum[bh][ch][seg][d] = s;
}
__global__ __launch_bounds__(64) void cumsum_p2()
{
    const int bh = blockIdx.x, d = threadIdx.x;
    float run = 0.f;
#pragma unroll
    for (int ch = 0; ch < 16; ch++) {
        g_chpre[bh][ch][d] = run;
        run += g_segsum[bh][ch][0][d] + g_segsum[bh][ch][1][d] +
               g_segsum[bh][ch][2][d] + g_segsum[bh][ch][3][d];
    }
}
__global__ __launch_bounds__(256) void cumsum_p3()
{
    const int bh = blockIdx.x, ch = blockIdx.y;
    const int b = bh >> 3, h = bh & 7;
    const int t = threadIdx.x;
    const int d = t & 63, seg = t >> 6;
    const float* vb = g_v + (size_t)b * LL * DD + h * DKK;
    float* cb = g_ctx + (size_t)b * LL * DD + h * DKK;

    float off = g_chpre[bh][ch][d];
    for (int s = 0; s < seg; s++) off += g_segsum[bh][ch][s][d];

    const int l0 = ch * 128 + seg * 32;
    float acc = off;
#pragma unroll 4
    for (int l = l0; l < l0 + 32; l++) {
        acc += vb[(size_t)l * DD + d];
        cb[(size_t)l * DD + d] = acc;
    }
}

// ---------------------------------------------------------------------------
extern "C" void kernel_launch(void* const* d_in, const int* in_sizes, int n_in,
                              void* d_out, int out_size)
{
    const float* queries = (const float*)d_in[0];
    const float* keys    = (const float*)d_in[1];
    const float* values  = (const float*)d_in[2];
    const int*   index_sample = (const int*)d_in[3];
    const float* Wq = (const float*)d_in[4];
    const float* bq = (const float*)d_in[5];
    const float* Wk = (const float*)d_in[6];
    const float* bk = (const float*)d_in[7];
    const float* Wv = (const float*)d_in[8];
    const float* bv = (const float*)d_in[9];
    const float* Wo = (const float*)d_in[10];
    const float* bo = (const float*)d_in[11];
    float* out = (float*)d_out;

    cudaFuncSetAttribute(hgemm_qkv, cudaFuncAttributeMaxDynamicSharedMemorySize, GSMEM);
    cudaFuncSetAttribute(hgemm_out, cudaFuncAttributeMaxDynamicSharedMemorySize, GSMEM);

    transpose_split_kernel<<<dim3(16, 16, 4), dim3(32, 8)>>>(Wq, Wk, Wv, Wo);

    hgemm_qkv<<<dim3(DD / 128, MTOT / 128, 3), 256, GSMEM>>>(queries, keys, values,
                                                             bq, bk, bv);

    probe_kernel<<<(BB * HH * LL * 32) / 256, 256>>>(index_sample);
    topk_p1<<<dim3(BH, 8), 256>>>();
    topk_p2<<<BH, 192>>>();
    cumsum_p1<<<dim3(BH, 16), 256>>>();
    cumsum_p2<<<BH, 64>>>();
    cumsum_p3<<<dim3(BH, 16), 256>>>();
    attn_kernel<<<BH * (UU / QG), 256>>>();   // overwrites ctx rows at top-k

    hgemm_out<<<dim3(DD / 128, MTOT / 128, 1), 256, GSMEM>>>(bo, out);
}

// round 16
// speedup vs baseline: 1.0510x; 1.0510x over previous
#include <cuda_runtime.h>
#include <cuda_bf16.h>
#include <cuda_fp16.h>
#include <math.h>
#include <stdint.h>

// Problem constants
#define BB 4
#define LL 2048
#define DD 512
#define HH 8
#define DKK 64
#define UU 24
#define BH (BB*HH)
#define MTOT (BB*LL)     // 8192 rows per GEMM

// ---------------- scratch (device globals; no allocation allowed) ----------
__device__ float g_q[BB*HH*LL*DKK];     // (B,H,L,DK)
__device__ float g_k[BB*HH*LL*DKK];
__device__ float g_v[BB*HH*LL*DKK];
__device__ float g_m[BB*HH*LL];
__device__ int   g_top[BB*HH*UU];
__device__ float g_ctx[BB*LL*DD];       // (b, l, h*DK+dk)

// pre-split transposed weights W^T[n][k]: bf16 hi/lo for Wq,Wk; fp16 for Wv,Wo
__device__ __nv_bfloat16 g_wh[2][DD*DD];
__device__ __nv_bfloat16 g_wl[2][DD*DD];
__device__ __half        g_wf[2][DD*DD];

// cumsum scratch
__device__ float g_segsum[BH][16][4][DKK];
__device__ float g_chpre[BH][16][DKK];

// =========================== helpers =======================================
__device__ __forceinline__ uint32_t smem_u32(const void* p) {
    uint32_t a;
    asm("{ .reg .u64 t; cvta.to.shared.u64 t, %1; cvt.u32.u64 %0, t; }"
        : "=r"(a) : "l"(p));
    return a;
}
__device__ __forceinline__ void cpasync16(uint32_t saddr, const void* gptr) {
    asm volatile("cp.async.cg.shared.global [%0], [%1], 16;"
                 :: "r"(saddr), "l"(__cvta_generic_to_global(gptr)) : "memory");
}
__device__ __forceinline__ void cp_commit() {
    asm volatile("cp.async.commit_group;" ::: "memory");
}
template<int N>
__device__ __forceinline__ void cp_wait() {
    asm volatile("cp.async.wait_group %0;" :: "n"(N) : "memory");
}
template<int F16>
__device__ __forceinline__ void mma_any(float& c0, float& c1, float& c2, float& c3,
                                        uint32_t a0, uint32_t a1, uint32_t a2, uint32_t a3,
                                        uint32_t b0, uint32_t b1) {
    if (F16)
        asm volatile("mma.sync.aligned.m16n8k16.row.col.f32.f16.f16.f32 "
                     "{%0,%1,%2,%3}, {%4,%5,%6,%7}, {%8,%9}, {%0,%1,%2,%3};"
                     : "+f"(c0), "+f"(c1), "+f"(c2), "+f"(c3)
                     : "r"(a0), "r"(a1), "r"(a2), "r"(a3), "r"(b0), "r"(b1));
    else
        asm volatile("mma.sync.aligned.m16n8k16.row.col.f32.bf16.bf16.f32 "
                     "{%0,%1,%2,%3}, {%4,%5,%6,%7}, {%8,%9}, {%0,%1,%2,%3};"
                     : "+f"(c0), "+f"(c1), "+f"(c2), "+f"(c3)
                     : "r"(a0), "r"(a1), "r"(a2), "r"(a3), "r"(b0), "r"(b1));
}
__device__ __forceinline__ void ldsm4(uint32_t& r0, uint32_t& r1, uint32_t& r2, uint32_t& r3,
                                      uint32_t addr) {
    asm volatile("ldmatrix.sync.aligned.m8n8.x4.shared.b16 {%0,%1,%2,%3}, [%4];"
                 : "=r"(r0), "=r"(r1), "=r"(r2), "=r"(r3) : "r"(addr));
}
__device__ __forceinline__ void split2(float x, __nv_bfloat16& h, __nv_bfloat16& l) {
    h = __float2bfloat16_rn(x);
    l = __float2bfloat16_rn(x - __bfloat162float(h));
}
__device__ __forceinline__ uint32_t pack2(__nv_bfloat16 a, __nv_bfloat16 b) {
    return (uint32_t)__bfloat16_as_ushort(a) | ((uint32_t)__bfloat16_as_ushort(b) << 16);
}
__device__ __forceinline__ void split2h(float x, __half& h, __half& l) {
    h = __float2half_rn(x);
    l = __float2half_rn(x - __half2float(h));
}
__device__ __forceinline__ uint32_t pack2h(__half a, __half b) {
    return (uint32_t)__half_as_ushort(a) | ((uint32_t)__half_as_ushort(b) << 16);
}

// W[k][n] -> W^T[n][k]: bf16 hi/lo (z=0,1: Wq,Wk), fp16 (z=2,3: Wv,Wo)
__global__ __launch_bounds__(256) void transpose_split_kernel(const float* __restrict__ Wq,
                                                              const float* __restrict__ Wk,
                                                              const float* __restrict__ Wv,
                                                              const float* __restrict__ Wo)
{
    __shared__ float tile[32][33];
    const int z = blockIdx.z;
    const float* W = (z == 0) ? Wq : (z == 1) ? Wk : (z == 2) ? Wv : Wo;
    const int k0 = blockIdx.y * 32, n0 = blockIdx.x * 32;
#pragma unroll
    for (int r = 0; r < 32; r += 8)
        tile[threadIdx.y + r][threadIdx.x] = W[(size_t)(k0 + threadIdx.y + r) * DD + n0 + threadIdx.x];
    __syncthreads();
#pragma unroll
    for (int r = 0; r < 32; r += 8) {
        const int n = n0 + threadIdx.y + r, k = k0 + threadIdx.x;
        const float w = tile[threadIdx.x][threadIdx.y + r];
        if (z < 2) {
            __nv_bfloat16 h, l;
            split2(w, h, l);
            g_wh[z][(size_t)n * DD + k] = h;
            g_wl[z][(size_t)n * DD + k] = l;
        } else {
            g_wf[z - 2][(size_t)n * DD + k] = __float2half_rn(w);
        }
    }
}

// ====== HMMA GEMM: 128x128 tile, BK=32, 2-stage, 1 sync/chunk, occ=2 =======
#define STG 40
#define ARRB (128*STG*2)
#define OFF_AH 0
#define OFF_AL (ARRB)
#define OFF_BH (2*ARRB)
#define OFF_BL (3*ARRB)
#define STAGE_B (4*ARRB)                // 40960
#define GSMEM (2*STAGE_B)               // 81920 -> 2 CTAs/SM

template<int F16>
__device__ __forceinline__ void split_sts(char* stagebase, int lrow, int lhalf,
                                          const float4* v4)
{
    uint16_t* ah = (uint16_t*)(stagebase + OFF_AH);
    uint16_t* al = (uint16_t*)(stagebase + OFF_AL);
#pragma unroll
    for (int qq = 0; qq < 4; qq++) {
        const float4 v = v4[qq];
        uint2 uh, ul;
        if (F16) {
            __half h0, h1, h2, h3, l0, l1, l2, l3;
            split2h(v.x, h0, l0); split2h(v.y, h1, l1);
            split2h(v.z, h2, l2); split2h(v.w, h3, l3);
            uh.x = pack2h(h0, h1); uh.y = pack2h(h2, h3);
            ul.x = pack2h(l0, l1); ul.y = pack2h(l2, l3);
        } else {
            __nv_bfloat16 h0, h1, h2, h3, l0, l1, l2, l3;
            split2(v.x, h0, l0); split2(v.y, h1, l1);
            split2(v.z, h2, l2); split2(v.w, h3, l3);
            uh.x = pack2(h0, h1); uh.y = pack2(h2, h3);
            ul.x = pack2(l0, l1); ul.y = pack2(l2, l3);
        }
        *(uint2*)(ah + lrow * STG + lhalf + qq * 4) = uh;
        *(uint2*)(al + lrow * STG + lhalf + qq * 4) = ul;
    }
}

template<int F16>
__device__ __forceinline__ void load_B(uint32_t s, const uint16_t* __restrict__ Bh,
                                       const uint16_t* __restrict__ Bl,
                                       int n0, int k0, int tid)
{
#pragma unroll
    for (int rep = 0; rep < 2; rep++) {
        const int c = tid + rep * 256;
        const int row = c >> 2, kp = (c & 3) * 8;
        cpasync16(s + OFF_BH + (uint32_t)(row * STG + kp) * 2,
                  Bh + (size_t)(n0 + row) * DD + k0 + kp);
    }
    if (!F16) {
#pragma unroll
        for (int rep = 0; rep < 2; rep++) {
            const int c = tid + rep * 256;
            const int row = c >> 2, kp = (c & 3) * 8;
            cpasync16(s + OFF_BL + (uint32_t)(row * STG + kp) * 2,
                      Bl + (size_t)(n0 + row) * DD + k0 + kp);
        }
    }
    cp_commit();
}

template<int SCATTER, int F16>
__device__ __forceinline__ void gemm_core(const float* __restrict__ A,
                                          const uint16_t* __restrict__ Bh,
                                          const uint16_t* __restrict__ Bl,
                                          const float* __restrict__ bias,
                                          float* __restrict__ dst, char* smraw,
                                          int m0, int n0)
{
    const int tid = threadIdx.x;
    const uint32_t sbase = smem_u32(smraw);

    const int wid = tid >> 5, lane = tid & 31;
    const int wm = (wid >> 2) * 64;
    const int wn = (wid & 3) * 32;
    const int g  = lane >> 2;
    const int q2 = (lane & 3) * 2;

    const int aRow = wm + (lane & 7) + ((lane >> 3) & 1) * 8;
    const int aColE = (lane >> 4) * 8;
    const int bRow = wn + (lane & 7) + ((lane >> 4) & 1) * 8;
    const int bColE = ((lane >> 3) & 1) * 8;

    const int lrow = tid >> 1, lhalf = (tid & 1) * 16;
    const float* Arow = A + (size_t)(m0 + lrow) * DD + lhalf;

    float acc[4][4][4];
#pragma unroll
    for (int i = 0; i < 4; i++)
#pragma unroll
        for (int j = 0; j < 4; j++)
#pragma unroll
            for (int r = 0; r < 4; r++) acc[i][j][r] = 0.f;

    float4 areg[4];

#pragma unroll
    for (int qq = 0; qq < 4; qq++) areg[qq] = *(const float4*)(Arow + qq * 4);
    split_sts<F16>(smraw, lrow, lhalf, areg);
    load_B<F16>(sbase, Bh, Bl, n0, 0, tid);

    for (int c = 0; c < 16; c++) {
        cp_wait<0>();
        __syncthreads();

        if (c < 15) {
            const int k1 = (c + 1) * 32;
#pragma unroll
            for (int qq = 0; qq < 4; qq++)
                areg[qq] = *(const float4*)(Arow + k1 + qq * 4);
            load_B<F16>(sbase + (uint32_t)((c + 1) & 1) * STAGE_B, Bh, Bl, n0, k1, tid);
        }

        const uint32_t stb = sbase + (uint32_t)(c & 1) * STAGE_B;
        const uint32_t aH = stb + OFF_AH + (uint32_t)(aRow * STG + aColE) * 2;
        const uint32_t aL = stb + OFF_AL + (uint32_t)(aRow * STG + aColE) * 2;
        const uint32_t bH = stb + OFF_BH + (uint32_t)(bRow * STG + bColE) * 2;
        const uint32_t bL = stb + OFF_BL + (uint32_t)(bRow * STG + bColE) * 2;

#pragma unroll
        for (int ks = 0; ks < 32; ks += 16) {
            uint32_t ah4[4][4], al4[4][4], bh4[2][4], bl4[2][4];
#pragma unroll
            for (int i = 0; i < 4; i++)
                ldsm4(ah4[i][0], ah4[i][1], ah4[i][2], ah4[i][3],
                      aH + (uint32_t)(i * 16 * STG + ks) * 2);
#pragma unroll
            for (int jp = 0; jp < 2; jp++)
                ldsm4(bh4[jp][0], bh4[jp][1], bh4[jp][2], bh4[jp][3],
                      bH + (uint32_t)(jp * 16 * STG + ks) * 2);
            if (!F16) {
#pragma unroll
                for (int jp = 0; jp < 2; jp++)
                    ldsm4(bl4[jp][0], bl4[jp][1], bl4[jp][2], bl4[jp][3],
                          bL + (uint32_t)(jp * 16 * STG + ks) * 2);
            }
#pragma unroll
            for (int i = 0; i < 4; i++)
                ldsm4(al4[i][0], al4[i][1], al4[i][2], al4[i][3],
                      aL + (uint32_t)(i * 16 * STG + ks) * 2);

#pragma unroll
            for (int i = 0; i < 4; i++)
#pragma unroll
                for (int j = 0; j < 4; j++) {
                    const int jp = j >> 1, jo = (j & 1) * 2;
                    mma_any<F16>(acc[i][j][0], acc[i][j][1], acc[i][j][2], acc[i][j][3],
                                 ah4[i][0], ah4[i][1], ah4[i][2], ah4[i][3],
                                 bh4[jp][jo], bh4[jp][jo + 1]);
                }
            if (!F16) {
#pragma unroll
                for (int i = 0; i < 4; i++)
#pragma unroll
                    for (int j = 0; j < 4; j++) {
                        const int jp = j >> 1, jo = (j & 1) * 2;
                        mma_any<F16>(acc[i][j][0], acc[i][j][1], acc[i][j][2], acc[i][j][3],
                                     ah4[i][0], ah4[i][1], ah4[i][2], ah4[i][3],
                                     bl4[jp][jo], bl4[jp][jo + 1]);
                    }
            }
#pragma unroll
            for (int i = 0; i < 4; i++)
#pragma unroll
                for (int j = 0; j < 4; j++) {
                    const int jp = j >> 1, jo = (j & 1) * 2;
                    mma_any<F16>(acc[i][j][0], acc[i][j][1], acc[i][j][2], acc[i][j][3],
                                 al4[i][0], al4[i][1], al4[i][2], al4[i][3],
                                 bh4[jp][jo], bh4[jp][jo + 1]);
                }
        }

        if (c < 15)
            split_sts<F16>(smraw + ((c + 1) & 1) * STAGE_B, lrow, lhalf, areg);
    }

    // epilogue
#pragma unroll
    for (int i = 0; i < 4; i++) {
#pragma unroll
        for (int j = 0; j < 4; j++) {
            const int gm0 = m0 + wm + i * 16 + g;
            const int gn  = n0 + wn + j * 8 + q2;
            const float b0 = bias[gn], b1 = bias[gn + 1];
            const float v0 = acc[i][j][0] + b0, v1 = acc[i][j][1] + b1;
            const float v2 = acc[i][j][2] + b0, v3 = acc[i][j][3] + b1;
            if (SCATTER == 0) {
                float* p0 = dst + (size_t)gm0 * DD + gn;
                p0[0] = v0; p0[1] = v1;
                float* p1 = dst + (size_t)(gm0 + 8) * DD + gn;
                p1[0] = v2; p1[1] = v3;
            } else {
                const int h = gn >> 6, dk = gn & 63;
                {
                    const int b = gm0 >> 11, l = gm0 & 2047;
                    float* p = dst + (((size_t)(b * HH + h)) * LL + l) * DKK + dk;
                    p[0] = v0; p[1] = v1;
                }
                {
                    const int gm1 = gm0 + 8;
                    const int b = gm1 >> 11, l = gm1 & 2047;
                    float* p = dst + (((size_t)(b * HH + h)) * LL + l) * DKK + dk;
                    p[0] = v2; p[1] = v3;
                }
            }
        }
    }
}

// merged Q/K/V projections: z=0,1 -> bf16 3-term; z=2 -> fp16 2-term
__global__ __launch_bounds__(256, 2) void hgemm_qkv(const float* __restrict__ q,
                                                    const float* __restrict__ k,
                                                    const float* __restrict__ v,
                                                    const float* __restrict__ bq,
                                                    const float* __restrict__ bk,
                                                    const float* __restrict__ bv)
{
    extern __shared__ char smraw[];
    const int z = blockIdx.z;
    const int m0 = blockIdx.y * 128, n0 = blockIdx.x * 128;
    if (z < 2) {
        gemm_core<1, 0>((z == 0) ? q : k,
                        (const uint16_t*)g_wh[z], (const uint16_t*)g_wl[z],
                        (z == 0) ? bq : bk, (z == 0) ? g_q : g_k, smraw, m0, n0);
    } else {
        gemm_core<1, 1>(v, (const uint16_t*)g_wf[0], (const uint16_t*)g_wf[0],
                        bv, g_v, smraw, m0, n0);
    }
}

__global__ __launch_bounds__(256, 2) void hgemm_out(const float* __restrict__ bo,
                                                    float* __restrict__ outp)
{
    extern __shared__ char smraw[];
    gemm_core<0, 1>((const float*)g_ctx, (const uint16_t*)g_wf[1], (const uint16_t*)g_wf[1],
                    bo, outp, smraw, blockIdx.y * 128, blockIdx.x * 128);
}

// =========================== non-GEMM kernels ==============================
__global__ __launch_bounds__(256) void probe_kernel(const int* __restrict__ idx)
{
    const int w = (blockIdx.x * blockDim.x + threadIdx.x) >> 5;
    const int lane = threadIdx.x & 31;
    if (w >= BB * HH * LL) return;
    const int l = w & (LL - 1);
    const int bh = w >> 11;

    const float* qrow = g_q + (size_t)(bh * LL + l) * DKK;
    const float2 qv = *(const float2*)(qrow + lane * 2);
    const float* kbase = g_k + (size_t)bh * LL * DKK;
    const int* ip = idx + l * UU;
    const int myidx = (lane < UU) ? ip[lane] : 0;

    float mx = -INFINITY, sm = 0.f;
#pragma unroll 4
    for (int s = 0; s < UU; s++) {
        const int j = __shfl_sync(0xffffffffu, myidx, s);
        const float2 kk = *(const float2*)(kbase + (size_t)j * DKK + lane * 2);
        float p = qv.x * kk.x + qv.y * kk.y;
#pragma unroll
        for (int o = 16; o > 0; o >>= 1) p += __shfl_xor_sync(0xffffffffu, p, o);
        mx = fmaxf(mx, p);
        sm += p;
    }
    if (lane == 0) g_m[w] = mx - sm * (1.0f / LL);
}

__global__ __launch_bounds__(256) void topk_kernel()
{
    __shared__ float swv[8];
    __shared__ int   swi[8];
    __shared__ int   swin;
    const int bh = blockIdx.x;
    const int t = threadIdx.x;
    const int wid = t >> 5, lane = t & 31;

    float v[8];
#pragma unroll
    for (int j = 0; j < 8; j++) v[j] = g_m[(size_t)bh * LL + j * 256 + t];

    for (int iter = 0; iter < UU; iter++) {
        float bv = v[0]; int bj = 0;
#pragma unroll
        for (int j = 1; j < 8; j++) if (v[j] > bv) { bv = v[j]; bj = j; }
        int bi = bj * 256 + t;
#pragma unroll
        for (int o = 16; o > 0; o >>= 1) {
            const float ov = __shfl_xor_sync(0xffffffffu, bv, o);
            const int   oi = __shfl_xor_sync(0xffffffffu, bi, o);
            if (ov > bv || (ov == bv && oi < bi)) { bv = ov; bi = oi; }
        }
        if (lane == 0) { swv[wid] = bv; swi[wid] = bi; }
        __syncthreads();
        if (t == 0) {
            float mv = swv[0]; int mi = swi[0];
#pragma unroll
            for (int w = 1; w < 8; w++)
                if (swv[w] > mv || (swv[w] == mv && swi[w] < mi)) { mv = swv[w]; mi = swi[w]; }
            g_top[bh * UU + iter] = mi;
            swin = mi;
        }
        __syncthreads();
        const int win = swin;
        if ((win & 255) == t) v[win >> 8] = -INFINITY;
    }
}

// Batched sparse attention: QG=8 queries per block, dynamic smem, writes g_ctx
#define QG 8
#define ATTN_SMEM (QG*DKK*4 + QG*LL*4 + 256*4 + QG*4)   // 68640 bytes

__global__ __launch_bounds__(256) void attn_kernel()
{
    extern __shared__ char araw[];
    float (*qs)[DKK] = (float(*)[DKK])araw;
    float (*sc)[LL]  = (float(*)[LL])(araw + QG * DKK * 4);
    float* red       = (float*)(araw + QG * DKK * 4 + QG * LL * 4);
    int*   pos_s     = (int*)(araw + QG * DKK * 4 + QG * LL * 4 + 256 * 4);

    const int bh = blockIdx.x / (UU / QG);
    const int grp = blockIdx.x % (UU / QG);
    const int t = threadIdx.x;
    const int wid = t >> 5, lane = t & 31;
    const int b = bh >> 3, h = bh & 7;

    const float* kb = g_k + (size_t)bh * LL * DKK;
    const float* vb = g_v + (size_t)bh * LL * DKK;

    for (int idx = t; idx < QG * DKK; idx += 256) {
        const int u = idx >> 6, d = idx & 63;
        const int p = g_top[bh * UU + grp * QG + u];
        if (d == 0) pos_s[u] = p;
        qs[u][d] = g_q[((size_t)bh * LL + p) * DKK + d];
    }
    __syncthreads();

    const float scale = rsqrtf((float)DD);

    float lmax[QG];
#pragma unroll
    for (int u = 0; u < QG; u++) lmax[u] = -INFINITY;

    for (int j = t; j < LL; j += 256) {
        const float* kr = kb + (size_t)j * DKK;
        float dot[QG];
#pragma unroll
        for (int u = 0; u < QG; u++) dot[u] = 0.f;
#pragma unroll
        for (int d4 = 0; d4 < 16; d4++) {
            float4 kk = *(const float4*)(kr + d4 * 4);
#pragma unroll
            for (int u = 0; u < QG; u++) {
                dot[u] += qs[u][d4 * 4] * kk.x + qs[u][d4 * 4 + 1] * kk.y +
                          qs[u][d4 * 4 + 2] * kk.z + qs[u][d4 * 4 + 3] * kk.w;
            }
        }
#pragma unroll
        for (int u = 0; u < QG; u++) {
            const float s = (j > pos_s[u]) ? -INFINITY : dot[u] * scale;
            sc[u][j] = s;
            lmax[u] = fmaxf(lmax[u], s);
        }
    }
#pragma unroll
    for (int u = 0; u < QG; u++) {
        float m = lmax[u];
#pragma unroll
        for (int o = 16; o > 0; o >>= 1) m = fmaxf(m, __shfl_xor_sync(0xffffffffu, m, o));
        if (lane == 0) red[u * 8 + wid] = m;
    }
    __syncthreads();
    float mx[QG];
#pragma unroll
    for (int u = 0; u < QG; u++) {
        float m = -INFINITY;
#pragma unroll
        for (int w = 0; w < 8; w++) m = fmaxf(m, red[u * 8 + w]);
        mx[u] = m;
    }
    __syncthreads();

    float lsum[QG];
#pragma unroll
    for (int u = 0; u < QG; u++) lsum[u] = 0.f;
    for (int j = t; j < LL; j += 256) {
#pragma unroll
        for (int u = 0; u < QG; u++) {
            const float p = __expf(sc[u][j] - mx[u]);
            sc[u][j] = p;
            lsum[u] += p;
        }
    }
#pragma unroll
    for (int u = 0; u < QG; u++) {
        float s = lsum[u];
#pragma unroll
        for (int o = 16; o > 0; o >>= 1) s += __shfl_xor_sync(0xffffffffu, s, o);
        if (lane == 0) red[u * 8 + wid] = s;
    }
    __syncthreads();
    float inv[QG];
#pragma unroll
    for (int u = 0; u < QG; u++) {
        float s = 0.f;
#pragma unroll
        for (int w = 0; w < 8; w++) s += red[u * 8 + w];
        inv[u] = 1.0f / s;
    }
    __syncthreads();

    const int d = t & 63, g4 = t >> 6;
    float acc[QG];
#pragma unroll
    for (int u = 0; u < QG; u++) acc[u] = 0.f;
    const int j0 = g4 * (LL / 4), j1 = j0 + (LL / 4);
    for (int j = j0; j < j1; j++) {
        const float v = vb[(size_t)j * DKK + d];
#pragma unroll
        for (int u = 0; u < QG; u++) acc[u] += sc[u][j] * v;
    }
#pragma unroll
    for (int u = 0; u < QG; u++) {
        red[t] = acc[u];
        __syncthreads();
        if (t < DKK) {
            const float o = (red[t] + red[t + 64] + red[t + 128] + red[t + 192]) * inv[u];
            // direct write into ctx (cumsum ran before; top-k rows are distinct)
            g_ctx[((size_t)b * LL + pos_s[u]) * DD + h * DKK + t] = o;
        }
        __syncthreads();
    }
}

// ---- cumsum, 3-phase ------------------------------------------------------
__global__ __launch_bounds__(256) void cumsum_p1()
{
    const int bh = blockIdx.x, ch = blockIdx.y;
    const int t = threadIdx.x;
    const int d = t & 63, seg = t >> 6;
    const float* vb = g_v + (size_t)bh * LL * DKK;
    const int l0 = ch * 128 + seg * 32;
    float s = 0.f;
#pragma unroll 4
    for (int l = l0; l < l0 + 32; l++) s += vb[(size_t)l * DKK + d];
    g_segsum[bh][ch][seg][d] = s;
}
__global__ __launch_bounds__(64) void cumsum_p2()
{
    const int bh = blockIdx.x, d = threadIdx.x;
    float run = 0.f;
#pragma unroll
    for (int ch = 0; ch < 16; ch++) {
        g_chpre[bh][ch][d] = run;
        run += g_segsum[bh][ch][0][d] + g_segsum[bh][ch][1][d] +
               g_segsum[bh][ch][2][d] + g_segsum[bh][ch][3][d];
    }
}
__global__ __launch_bounds__(256) void cumsum_p3()
{
    const int bh = blockIdx.x, ch = blockIdx.y;
    const int b = bh >> 3, h = bh & 7;
    const int t = threadIdx.x;
    const int d = t & 63, seg = t >> 6;
    const float* vb = g_v + (size_t)bh * LL * DKK;

    float off = g_chpre[bh][ch][d];
    for (int s = 0; s < seg; s++) off += g_segsum[bh][ch][s][d];

    const int l0 = ch * 128 + seg * 32;
    float acc = off;
    float* cb = g_ctx + (size_t)b * LL * DD + h * DKK;
#pragma unroll 4
    for (int l = l0; l < l0 + 32; l++) {
        acc += vb[(size_t)l * DKK + d];
        cb[(size_t)l * DD + d] = acc;
    }
}

// ---------------------------------------------------------------------------
extern "C" void kernel_launch(void* const* d_in, const int* in_sizes, int n_in,
                              void* d_out, int out_size)
{
    const float* queries = (const float*)d_in[0];
    const float* keys    = (const float*)d_in[1];
    const float* values  = (const float*)d_in[2];
    const int*   index_sample = (const int*)d_in[3];
    const float* Wq = (const float*)d_in[4];
    const float* bq = (const float*)d_in[5];
    const float* Wk = (const float*)d_in[6];
    const float* bk = (const float*)d_in[7];
    const float* Wv = (const float*)d_in[8];
    const float* bv = (const float*)d_in[9];
    const float* Wo = (const float*)d_in[10];
    const float* bo = (const float*)d_in[11];
    float* out = (float*)d_out;

    cudaFuncSetAttribute(hgemm_qkv, cudaFuncAttributeMaxDynamicSharedMemorySize, GSMEM);
    cudaFuncSetAttribute(hgemm_out, cudaFuncAttributeMaxDynamicSharedMemorySize, GSMEM);
    cudaFuncSetAttribute(attn_kernel, cudaFuncAttributeMaxDynamicSharedMemorySize, ATTN_SMEM);

    transpose_split_kernel<<<dim3(16, 16, 4), dim3(32, 8)>>>(Wq, Wk, Wv, Wo);

    hgemm_qkv<<<dim3(DD / 128, MTOT / 128, 3), 256, GSMEM>>>(queries, keys, values,
                                                             bq, bk, bv);

    probe_kernel<<<(BB * HH * LL * 32) / 256, 256>>>(index_sample);
    topk_kernel<<<BH, 256>>>();
    cumsum_p1<<<dim3(BH, 16), 256>>>();
    cumsum_p2<<<BH, 64>>>();
    cumsum_p3<<<dim3(BH, 16), 256>>>();
    attn_kernel<<<BH * (UU / QG), 256, ATTN_SMEM>>>();   // overwrites ctx top-k rows

    hgemm_out<<<dim3(DD / 128, MTOT / 128, 1), 256, GSMEM>>>(bo, out);
}

// round 17
// speedup vs baseline: 1.1379x; 1.0827x over previous
#include <cuda_runtime.h>
#include <cuda_bf16.h>
#include <cuda_fp16.h>
#include <math.h>
#include <stdint.h>

// Problem constants
#define BB 4
#define LL 2048
#define DD 512
#define HH 8
#define DKK 64
#define UU 24
#define BH (BB*HH)
#define MTOT (BB*LL)     // 8192 rows per GEMM

// ---------------- scratch (device globals; no allocation allowed) ----------
__device__ float g_q[BB*HH*LL*DKK];     // (B,H,L,DK)
__device__ float g_k[BB*HH*LL*DKK];
__device__ float g_v[BB*HH*LL*DKK];
__device__ float g_m[BB*HH*LL];
__device__ int   g_top[BB*HH*UU];
__device__ float g_ctx[BB*LL*DD];       // (b, l, h*DK+dk)

// pre-split transposed weights W^T[n][k]: bf16 hi/lo for Wq,Wk; fp16 for Wv,Wo
__device__ __nv_bfloat16 g_wh[2][DD*DD];
__device__ __nv_bfloat16 g_wl[2][DD*DD];
__device__ __half        g_wf[2][DD*DD];

// cumsum scratch
__device__ float g_segsum[BH][16][4][DKK];
__device__ float g_chpre[BH][16][DKK];

// =========================== helpers =======================================
__device__ __forceinline__ uint32_t smem_u32(const void* p) {
    uint32_t a;
    asm("{ .reg .u64 t; cvta.to.shared.u64 t, %1; cvt.u32.u64 %0, t; }"
        : "=r"(a) : "l"(p));
    return a;
}
__device__ __forceinline__ void cpasync16(uint32_t saddr, const void* gptr) {
    asm volatile("cp.async.cg.shared.global [%0], [%1], 16;"
                 :: "r"(saddr), "l"(__cvta_generic_to_global(gptr)) : "memory");
}
__device__ __forceinline__ void cp_commit() {
    asm volatile("cp.async.commit_group;" ::: "memory");
}
template<int N>
__device__ __forceinline__ void cp_wait() {
    asm volatile("cp.async.wait_group %0;" :: "n"(N) : "memory");
}
template<int F16>
__device__ __forceinline__ void mma_any(float& c0, float& c1, float& c2, float& c3,
                                        uint32_t a0, uint32_t a1, uint32_t a2, uint32_t a3,
                                        uint32_t b0, uint32_t b1) {
    if (F16)
        asm volatile("mma.sync.aligned.m16n8k16.row.col.f32.f16.f16.f32 "
                     "{%0,%1,%2,%3}, {%4,%5,%6,%7}, {%8,%9}, {%0,%1,%2,%3};"
                     : "+f"(c0), "+f"(c1), "+f"(c2), "+f"(c3)
                     : "r"(a0), "r"(a1), "r"(a2), "r"(a3), "r"(b0), "r"(b1));
    else
        asm volatile("mma.sync.aligned.m16n8k16.row.col.f32.bf16.bf16.f32 "
                     "{%0,%1,%2,%3}, {%4,%5,%6,%7}, {%8,%9}, {%0,%1,%2,%3};"
                     : "+f"(c0), "+f"(c1), "+f"(c2), "+f"(c3)
                     : "r"(a0), "r"(a1), "r"(a2), "r"(a3), "r"(b0), "r"(b1));
}
__device__ __forceinline__ void ldsm4(uint32_t& r0, uint32_t& r1, uint32_t& r2, uint32_t& r3,
                                      uint32_t addr) {
    asm volatile("ldmatrix.sync.aligned.m8n8.x4.shared.b16 {%0,%1,%2,%3}, [%4];"
                 : "=r"(r0), "=r"(r1), "=r"(r2), "=r"(r3) : "r"(addr));
}
__device__ __forceinline__ void split2(float x, __nv_bfloat16& h, __nv_bfloat16& l) {
    h = __float2bfloat16_rn(x);
    l = __float2bfloat16_rn(x - __bfloat162float(h));
}
__device__ __forceinline__ uint32_t pack2(__nv_bfloat16 a, __nv_bfloat16 b) {
    return (uint32_t)__bfloat16_as_ushort(a) | ((uint32_t)__bfloat16_as_ushort(b) << 16);
}
__device__ __forceinline__ void split2h(float x, __half& h, __half& l) {
    h = __float2half_rn(x);
    l = __float2half_rn(x - __half2float(h));
}
__device__ __forceinline__ uint32_t pack2h(__half a, __half b) {
    return (uint32_t)__half_as_ushort(a) | ((uint32_t)__half_as_ushort(b) << 16);
}

// W[k][n] -> W^T[n][k]: bf16 hi/lo (z=0,1: Wq,Wk), fp16 (z=2,3: Wv,Wo)
__global__ __launch_bounds__(256) void transpose_split_kernel(const float* __restrict__ Wq,
                                                              const float* __restrict__ Wk,
                                                              const float* __restrict__ Wv,
                                                              const float* __restrict__ Wo)
{
    __shared__ float tile[32][33];
    const int z = blockIdx.z;
    const float* W = (z == 0) ? Wq : (z == 1) ? Wk : (z == 2) ? Wv : Wo;
    const int k0 = blockIdx.y * 32, n0 = blockIdx.x * 32;
#pragma unroll
    for (int r = 0; r < 32; r += 8)
        tile[threadIdx.y + r][threadIdx.x] = W[(size_t)(k0 + threadIdx.y + r) * DD + n0 + threadIdx.x];
    __syncthreads();
#pragma unroll
    for (int r = 0; r < 32; r += 8) {
        const int n = n0 + threadIdx.y + r, k = k0 + threadIdx.x;
        const float w = tile[threadIdx.x][threadIdx.y + r];
        if (z < 2) {
            __nv_bfloat16 h, l;
            split2(w, h, l);
            g_wh[z][(size_t)n * DD + k] = h;
            g_wl[z][(size_t)n * DD + k] = l;
        } else {
            g_wf[z - 2][(size_t)n * DD + k] = __float2half_rn(w);
        }
    }
}

// ====== HMMA GEMM: 128x128 tile, BK=32, 2-stage, 1 sync/chunk, occ=2 =======
#define STG 40
#define ARRB (128*STG*2)
#define OFF_AH 0
#define OFF_AL (ARRB)
#define OFF_BH (2*ARRB)
#define OFF_BL (3*ARRB)
#define STAGE_B (4*ARRB)                // 40960
#define GSMEM (2*STAGE_B)               // 81920 -> 2 CTAs/SM

template<int F16>
__device__ __forceinline__ void split_sts(char* stagebase, int lrow, int lhalf,
                                          const float4* v4)
{
    uint16_t* ah = (uint16_t*)(stagebase + OFF_AH);
    uint16_t* al = (uint16_t*)(stagebase + OFF_AL);
#pragma unroll
    for (int qq = 0; qq < 4; qq++) {
        const float4 v = v4[qq];
        uint2 uh, ul;
        if (F16) {
            __half h0, h1, h2, h3, l0, l1, l2, l3;
            split2h(v.x, h0, l0); split2h(v.y, h1, l1);
            split2h(v.z, h2, l2); split2h(v.w, h3, l3);
            uh.x = pack2h(h0, h1); uh.y = pack2h(h2, h3);
            ul.x = pack2h(l0, l1); ul.y = pack2h(l2, l3);
        } else {
            __nv_bfloat16 h0, h1, h2, h3, l0, l1, l2, l3;
            split2(v.x, h0, l0); split2(v.y, h1, l1);
            split2(v.z, h2, l2); split2(v.w, h3, l3);
            uh.x = pack2(h0, h1); uh.y = pack2(h2, h3);
            ul.x = pack2(l0, l1); ul.y = pack2(l2, l3);
        }
        *(uint2*)(ah + lrow * STG + lhalf + qq * 4) = uh;
        *(uint2*)(al + lrow * STG + lhalf + qq * 4) = ul;
    }
}

template<int F16>
__device__ __forceinline__ void load_B(uint32_t s, const uint16_t* __restrict__ Bh,
                                       const uint16_t* __restrict__ Bl,
                                       int n0, int k0, int tid)
{
#pragma unroll
    for (int rep = 0; rep < 2; rep++) {
        const int c = tid + rep * 256;
        const int row = c >> 2, kp = (c & 3) * 8;
        cpasync16(s + OFF_BH + (uint32_t)(row * STG + kp) * 2,
                  Bh + (size_t)(n0 + row) * DD + k0 + kp);
    }
    if (!F16) {
#pragma unroll
        for (int rep = 0; rep < 2; rep++) {
            const int c = tid + rep * 256;
            const int row = c >> 2, kp = (c & 3) * 8;
            cpasync16(s + OFF_BL + (uint32_t)(row * STG + kp) * 2,
                      Bl + (size_t)(n0 + row) * DD + k0 + kp);
        }
    }
    cp_commit();
}

template<int SCATTER, int F16>
__device__ __forceinline__ void gemm_core(const float* __restrict__ A,
                                          const uint16_t* __restrict__ Bh,
                                          const uint16_t* __restrict__ Bl,
                                          const float* __restrict__ bias,
                                          float* __restrict__ dst, char* smraw,
                                          int m0, int n0)
{
    const int tid = threadIdx.x;
    const uint32_t sbase = smem_u32(smraw);

    const int wid = tid >> 5, lane = tid & 31;
    const int wm = (wid >> 2) * 64;
    const int wn = (wid & 3) * 32;
    const int g  = lane >> 2;
    const int q2 = (lane & 3) * 2;

    const int aRow = wm + (lane & 7) + ((lane >> 3) & 1) * 8;
    const int aColE = (lane >> 4) * 8;
    const int bRow = wn + (lane & 7) + ((lane >> 4) & 1) * 8;
    const int bColE = ((lane >> 3) & 1) * 8;

    const int lrow = tid >> 1, lhalf = (tid & 1) * 16;
    const float* Arow = A + (size_t)(m0 + lrow) * DD + lhalf;

    float acc[4][4][4];
#pragma unroll
    for (int i = 0; i < 4; i++)
#pragma unroll
        for (int j = 0; j < 4; j++)
#pragma unroll
            for (int r = 0; r < 4; r++) acc[i][j][r] = 0.f;

    float4 areg[4];

#pragma unroll
    for (int qq = 0; qq < 4; qq++) areg[qq] = *(const float4*)(Arow + qq * 4);
    split_sts<F16>(smraw, lrow, lhalf, areg);
    load_B<F16>(sbase, Bh, Bl, n0, 0, tid);

    for (int c = 0; c < 16; c++) {
        cp_wait<0>();
        __syncthreads();

        if (c < 15) {
            const int k1 = (c + 1) * 32;
#pragma unroll
            for (int qq = 0; qq < 4; qq++)
                areg[qq] = *(const float4*)(Arow + k1 + qq * 4);
            load_B<F16>(sbase + (uint32_t)((c + 1) & 1) * STAGE_B, Bh, Bl, n0, k1, tid);
        }

        const uint32_t stb = sbase + (uint32_t)(c & 1) * STAGE_B;
        const uint32_t aH = stb + OFF_AH + (uint32_t)(aRow * STG + aColE) * 2;
        const uint32_t aL = stb + OFF_AL + (uint32_t)(aRow * STG + aColE) * 2;
        const uint32_t bH = stb + OFF_BH + (uint32_t)(bRow * STG + bColE) * 2;
        const uint32_t bL = stb + OFF_BL + (uint32_t)(bRow * STG + bColE) * 2;

#pragma unroll
        for (int ks = 0; ks < 32; ks += 16) {
            uint32_t ah4[4][4], al4[4][4], bh4[2][4], bl4[2][4];
#pragma unroll
            for (int i = 0; i < 4; i++)
                ldsm4(ah4[i][0], ah4[i][1], ah4[i][2], ah4[i][3],
                      aH + (uint32_t)(i * 16 * STG + ks) * 2);
#pragma unroll
            for (int jp = 0; jp < 2; jp++)
                ldsm4(bh4[jp][0], bh4[jp][1], bh4[jp][2], bh4[jp][3],
                      bH + (uint32_t)(jp * 16 * STG + ks) * 2);
            if (!F16) {
#pragma unroll
                for (int jp = 0; jp < 2; jp++)
                    ldsm4(bl4[jp][0], bl4[jp][1], bl4[jp][2], bl4[jp][3],
                          bL + (uint32_t)(jp * 16 * STG + ks) * 2);
            }
#pragma unroll
            for (int i = 0; i < 4; i++)
                ldsm4(al4[i][0], al4[i][1], al4[i][2], al4[i][3],
                      aL + (uint32_t)(i * 16 * STG + ks) * 2);

#pragma unroll
            for (int i = 0; i < 4; i++)
#pragma unroll
                for (int j = 0; j < 4; j++) {
                    const int jp = j >> 1, jo = (j & 1) * 2;
                    mma_any<F16>(acc[i][j][0], acc[i][j][1], acc[i][j][2], acc[i][j][3],
                                 ah4[i][0], ah4[i][1], ah4[i][2], ah4[i][3],
                                 bh4[jp][jo], bh4[jp][jo + 1]);
                }
            if (!F16) {
#pragma unroll
                for (int i = 0; i < 4; i++)
#pragma unroll
                    for (int j = 0; j < 4; j++) {
                        const int jp = j >> 1, jo = (j & 1) * 2;
                        mma_any<F16>(acc[i][j][0], acc[i][j][1], acc[i][j][2], acc[i][j][3],
                                     ah4[i][0], ah4[i][1], ah4[i][2], ah4[i][3],
                                     bl4[jp][jo], bl4[jp][jo + 1]);
                    }
            }
#pragma unroll
            for (int i = 0; i < 4; i++)
#pragma unroll
                for (int j = 0; j < 4; j++) {
                    const int jp = j >> 1, jo = (j & 1) * 2;
                    mma_any<F16>(acc[i][j][0], acc[i][j][1], acc[i][j][2], acc[i][j][3],
                                 al4[i][0], al4[i][1], al4[i][2], al4[i][3],
                                 bh4[jp][jo], bh4[jp][jo + 1]);
                }
        }

        if (c < 15)
            split_sts<F16>(smraw + ((c + 1) & 1) * STAGE_B, lrow, lhalf, areg);
    }

    // epilogue
#pragma unroll
    for (int i = 0; i < 4; i++) {
#pragma unroll
        for (int j = 0; j < 4; j++) {
            const int gm0 = m0 + wm + i * 16 + g;
            const int gn  = n0 + wn + j * 8 + q2;
            const float b0 = bias[gn], b1 = bias[gn + 1];
            const float v0 = acc[i][j][0] + b0, v1 = acc[i][j][1] + b1;
            const float v2 = acc[i][j][2] + b0, v3 = acc[i][j][3] + b1;
            if (SCATTER == 0) {
                float* p0 = dst + (size_t)gm0 * DD + gn;
                p0[0] = v0; p0[1] = v1;
                float* p1 = dst + (size_t)(gm0 + 8) * DD + gn;
                p1[0] = v2; p1[1] = v3;
            } else {
                const int h = gn >> 6, dk = gn & 63;
                {
                    const int b = gm0 >> 11, l = gm0 & 2047;
                    float* p = dst + (((size_t)(b * HH + h)) * LL + l) * DKK + dk;
                    p[0] = v0; p[1] = v1;
                }
                {
                    const int gm1 = gm0 + 8;
                    const int b = gm1 >> 11, l = gm1 & 2047;
                    float* p = dst + (((size_t)(b * HH + h)) * LL + l) * DKK + dk;
                    p[0] = v2; p[1] = v3;
                }
            }
        }
    }
}

// merged Q/K/V projections: z=0,1 -> bf16 3-term; z=2 -> fp16 2-term
__global__ __launch_bounds__(256, 2) void hgemm_qkv(const float* __restrict__ q,
                                                    const float* __restrict__ k,
                                                    const float* __restrict__ v,
                                                    const float* __restrict__ bq,
                                                    const float* __restrict__ bk,
                                                    const float* __restrict__ bv)
{
    extern __shared__ char smraw[];
    const int z = blockIdx.z;
    const int m0 = blockIdx.y * 128, n0 = blockIdx.x * 128;
    if (z < 2) {
        gemm_core<1, 0>((z == 0) ? q : k,
                        (const uint16_t*)g_wh[z], (const uint16_t*)g_wl[z],
                        (z == 0) ? bq : bk, (z == 0) ? g_q : g_k, smraw, m0, n0);
    } else {
        gemm_core<1, 1>(v, (const uint16_t*)g_wf[0], (const uint16_t*)g_wf[0],
                        bv, g_v, smraw, m0, n0);
    }
}

__global__ __launch_bounds__(256, 2) void hgemm_out(const float* __restrict__ bo,
                                                    float* __restrict__ outp)
{
    extern __shared__ char smraw[];
    gemm_core<0, 1>((const float*)g_ctx, (const uint16_t*)g_wf[1], (const uint16_t*)g_wf[1],
                    bo, outp, smraw, blockIdx.y * 128, blockIdx.x * 128);
}

// =========================== fused non-GEMM kernels ========================
#define PROBE_BLOCKS ((BB*HH*LL)/8)    // 8192 (8 warps = 8 queries per block)

// L1: probe (blocks 0..8191) + cumsum_p1 (blocks 8192..8703)
__global__ __launch_bounds__(256) void fused_probe_csum1(const int* __restrict__ idx)
{
    if (blockIdx.x < PROBE_BLOCKS) {
        // probe: warp = query; lane = (group g of 4 samples, dim-slice r of 8)
        const int w = (blockIdx.x * 256 + threadIdx.x) >> 5;
        const int lane = threadIdx.x & 31;
        const int l = w & (LL - 1);
        const int bh = w >> 11;
        const int gg = lane >> 3, r = lane & 7;

        const float* qrow = g_q + (size_t)(bh * LL + l) * DKK + r * 8;
        const float4 q0 = *(const float4*)qrow;
        const float4 q1 = *(const float4*)(qrow + 4);
        const float* kbase = g_k + (size_t)bh * LL * DKK;
        const int* ip = idx + l * UU;
        const int myidx = (lane < UU) ? ip[lane] : 0;

        float mx = -INFINITY, sm = 0.f;
#pragma unroll
        for (int s0 = 0; s0 < UU; s0 += 4) {
            const int j = __shfl_sync(0xffffffffu, myidx, s0 + gg);
            const float* kr = kbase + (size_t)j * DKK + r * 8;
            const float4 k0 = *(const float4*)kr;
            const float4 k1 = *(const float4*)(kr + 4);
            float p = q0.x * k0.x + q0.y * k0.y + q0.z * k0.z + q0.w * k0.w
                    + q1.x * k1.x + q1.y * k1.y + q1.z * k1.z + q1.w * k1.w;
            p += __shfl_xor_sync(0xffffffffu, p, 1);
            p += __shfl_xor_sync(0xffffffffu, p, 2);
            p += __shfl_xor_sync(0xffffffffu, p, 4);
            mx = fmaxf(mx, p);
            sm += p;
        }
        mx = fmaxf(mx, __shfl_xor_sync(0xffffffffu, mx, 8));
        mx = fmaxf(mx, __shfl_xor_sync(0xffffffffu, mx, 16));
        sm += __shfl_xor_sync(0xffffffffu, sm, 8);
        sm += __shfl_xor_sync(0xffffffffu, sm, 16);
        if (lane == 0) g_m[w] = mx - sm * (1.0f / LL);
    } else {
        // cumsum_p1
        const int bid = blockIdx.x - PROBE_BLOCKS;
        const int bh = bid >> 4, ch = bid & 15;
        const int t = threadIdx.x;
        const int d = t & 63, seg = t >> 6;
        const float* vb = g_v + (size_t)bh * LL * DKK;
        const int l0 = ch * 128 + seg * 32;
        float s = 0.f;
#pragma unroll 4
        for (int l = l0; l < l0 + 32; l++) s += vb[(size_t)l * DKK + d];
        g_segsum[bh][ch][seg][d] = s;
    }
}

// L2: topk (blocks 0..31) + cumsum_p2 (blocks 32..63)
__global__ __launch_bounds__(256) void fused_topk_csum2()
{
    if (blockIdx.x < BH) {
        __shared__ float swv[8];
        __shared__ int   swi[8];
        __shared__ int   swin;
        const int bh = blockIdx.x;
        const int t = threadIdx.x;
        const int wid = t >> 5, lane = t & 31;

        float v[8];
#pragma unroll
        for (int j = 0; j < 8; j++) v[j] = g_m[(size_t)bh * LL + j * 256 + t];

        for (int iter = 0; iter < UU; iter++) {
            float bv = v[0]; int bj = 0;
#pragma unroll
            for (int j = 1; j < 8; j++) if (v[j] > bv) { bv = v[j]; bj = j; }
            int bi = bj * 256 + t;
#pragma unroll
            for (int o = 16; o > 0; o >>= 1) {
                const float ov = __shfl_xor_sync(0xffffffffu, bv, o);
                const int   oi = __shfl_xor_sync(0xffffffffu, bi, o);
                if (ov > bv || (ov == bv && oi < bi)) { bv = ov; bi = oi; }
            }
            if (lane == 0) { swv[wid] = bv; swi[wid] = bi; }
            __syncthreads();
            if (t == 0) {
                float mv = swv[0]; int mi = swi[0];
#pragma unroll
                for (int w = 1; w < 8; w++)
                    if (swv[w] > mv || (swv[w] == mv && swi[w] < mi)) { mv = swv[w]; mi = swi[w]; }
                g_top[bh * UU + iter] = mi;
                swin = mi;
            }
            __syncthreads();
            const int win = swin;
            if ((win & 255) == t) v[win >> 8] = -INFINITY;
        }
    } else {
        // cumsum_p2 (64 active threads)
        const int bh = blockIdx.x - BH;
        const int d = threadIdx.x;
        if (d < DKK) {
            float run = 0.f;
#pragma unroll
            for (int ch = 0; ch < 16; ch++) {
                g_chpre[bh][ch][d] = run;
                run += g_segsum[bh][ch][0][d] + g_segsum[bh][ch][1][d] +
                       g_segsum[bh][ch][2][d] + g_segsum[bh][ch][3][d];
            }
        }
    }
}

// L3: attn (blocks 0..95) + cumsum_p3-with-skip (blocks 96..607)
// attn writes ONLY top-k rows of ctx; p3 writes all rows EXCEPT top-k rows.
#define QG 8
#define F3_ATTN_BLOCKS (BH*(UU/QG))    // 96
#define ATTN_SMEM (QG*DKK*4 + QG*LL*4 + 256*4 + QG*4)   // 68640 bytes

__global__ __launch_bounds__(256) void fused_attn_csum3()
{
    if (blockIdx.x < F3_ATTN_BLOCKS) {
        extern __shared__ char araw[];
        float (*qs)[DKK] = (float(*)[DKK])araw;
        float (*sc)[LL]  = (float(*)[LL])(araw + QG * DKK * 4);
        float* red       = (float*)(araw + QG * DKK * 4 + QG * LL * 4);
        int*   pos_s     = (int*)(araw + QG * DKK * 4 + QG * LL * 4 + 256 * 4);

        const int bh = blockIdx.x / (UU / QG);
        const int grp = blockIdx.x % (UU / QG);
        const int t = threadIdx.x;
        const int wid = t >> 5, lane = t & 31;
        const int b = bh >> 3, h = bh & 7;

        const float* kb = g_k + (size_t)bh * LL * DKK;
        const float* vb = g_v + (size_t)bh * LL * DKK;

        for (int idx2 = t; idx2 < QG * DKK; idx2 += 256) {
            const int u = idx2 >> 6, d = idx2 & 63;
            const int p = g_top[bh * UU + grp * QG + u];
            if (d == 0) pos_s[u] = p;
            qs[u][d] = g_q[((size_t)bh * LL + p) * DKK + d];
        }
        __syncthreads();

        const float scale = rsqrtf((float)DD);

        float lmax[QG];
#pragma unroll
        for (int u = 0; u < QG; u++) lmax[u] = -INFINITY;

        for (int j = t; j < LL; j += 256) {
            const float* kr = kb + (size_t)j * DKK;
            float dot[QG];
#pragma unroll
            for (int u = 0; u < QG; u++) dot[u] = 0.f;
#pragma unroll
            for (int d4 = 0; d4 < 16; d4++) {
                float4 kk = *(const float4*)(kr + d4 * 4);
#pragma unroll
                for (int u = 0; u < QG; u++) {
                    dot[u] += qs[u][d4 * 4] * kk.x + qs[u][d4 * 4 + 1] * kk.y +
                              qs[u][d4 * 4 + 2] * kk.z + qs[u][d4 * 4 + 3] * kk.w;
                }
            }
#pragma unroll
            for (int u = 0; u < QG; u++) {
                const float s = (j > pos_s[u]) ? -INFINITY : dot[u] * scale;
                sc[u][j] = s;
                lmax[u] = fmaxf(lmax[u], s);
            }
        }
#pragma unroll
        for (int u = 0; u < QG; u++) {
            float m = lmax[u];
#pragma unroll
            for (int o = 16; o > 0; o >>= 1) m = fmaxf(m, __shfl_xor_sync(0xffffffffu, m, o));
            if (lane == 0) red[u * 8 + wid] = m;
        }
        __syncthreads();
        float mx[QG];
#pragma unroll
        for (int u = 0; u < QG; u++) {
            float m = -INFINITY;
#pragma unroll
            for (int w = 0; w < 8; w++) m = fmaxf(m, red[u * 8 + w]);
            mx[u] = m;
        }
        __syncthreads();

        float lsum[QG];
#pragma unroll
        for (int u = 0; u < QG; u++) lsum[u] = 0.f;
        for (int j = t; j < LL; j += 256) {
#pragma unroll
            for (int u = 0; u < QG; u++) {
                const float p = __expf(sc[u][j] - mx[u]);
                sc[u][j] = p;
                lsum[u] += p;
            }
        }
#pragma unroll
        for (int u = 0; u < QG; u++) {
            float s = lsum[u];
#pragma unroll
            for (int o = 16; o > 0; o >>= 1) s += __shfl_xor_sync(0xffffffffu, s, o);
            if (lane == 0) red[u * 8 + wid] = s;
        }
        __syncthreads();
        float inv[QG];
#pragma unroll
        for (int u = 0; u < QG; u++) {
            float s = 0.f;
#pragma unroll
            for (int w = 0; w < 8; w++) s += red[u * 8 + w];
            inv[u] = 1.0f / s;
        }
        __syncthreads();

        const int d = t & 63, g4 = t >> 6;
        float acc[QG];
#pragma unroll
        for (int u = 0; u < QG; u++) acc[u] = 0.f;
        const int j0 = g4 * (LL / 4), j1 = j0 + (LL / 4);
        for (int j = j0; j < j1; j++) {
            const float v = vb[(size_t)j * DKK + d];
#pragma unroll
            for (int u = 0; u < QG; u++) acc[u] += sc[u][j] * v;
        }
#pragma unroll
        for (int u = 0; u < QG; u++) {
            red[t] = acc[u];
            __syncthreads();
            if (t < DKK) {
                const float o = (red[t] + red[t + 64] + red[t + 128] + red[t + 192]) * inv[u];
                g_ctx[((size_t)b * LL + pos_s[u]) * DD + h * DKK + t] = o;
            }
            __syncthreads();
        }
    } else {
        // cumsum_p3 with top-k skip (writes disjoint from attn's rows)
        __shared__ char flag[LL];
        const int bid = blockIdx.x - F3_ATTN_BLOCKS;
        const int bh = bid >> 4, ch = bid & 15;
        const int b = bh >> 3, h = bh & 7;
        const int t = threadIdx.x;

        for (int i = t; i < LL; i += 256) flag[i] = 0;
        __syncthreads();
        if (t < UU) flag[g_top[bh * UU + t]] = 1;
        __syncthreads();

        const int d = t & 63, seg = t >> 6;
        const float* vb = g_v + (size_t)bh * LL * DKK;

        float off = g_chpre[bh][ch][d];
        for (int s = 0; s < seg; s++) off += g_segsum[bh][ch][s][d];

        const int l0 = ch * 128 + seg * 32;
        float acc = off;
        float* cb = g_ctx + (size_t)b * LL * DD + h * DKK;
#pragma unroll 4
        for (int l = l0; l < l0 + 32; l++) {
            acc += vb[(size_t)l * DKK + d];
            if (!flag[l]) cb[(size_t)l * DD + d] = acc;
        }
    }
}

// ---------------------------------------------------------------------------
extern "C" void kernel_launch(void* const* d_in, const int* in_sizes, int n_in,
                              void* d_out, int out_size)
{
    const float* queries = (const float*)d_in[0];
    const float* keys    = (const float*)d_in[1];
    const float* values  = (const float*)d_in[2];
    const int*   index_sample = (const int*)d_in[3];
    const float* Wq = (const float*)d_in[4];
    const float* bq = (const float*)d_in[5];
    const float* Wk = (const float*)d_in[6];
    const float* bk = (const float*)d_in[7];
    const float* Wv = (const float*)d_in[8];
    const float* bv = (const float*)d_in[9];
    const float* Wo = (const float*)d_in[10];
    const float* bo = (const float*)d_in[11];
    float* out = (float*)d_out;

    cudaFuncSetAttribute(hgemm_qkv, cudaFuncAttributeMaxDynamicSharedMemorySize, GSMEM);
    cudaFuncSetAttribute(hgemm_out, cudaFuncAttributeMaxDynamicSharedMemorySize, GSMEM);
    cudaFuncSetAttribute(fused_attn_csum3, cudaFuncAttributeMaxDynamicSharedMemorySize, ATTN_SMEM);

    transpose_split_kernel<<<dim3(16, 16, 4), dim3(32, 8)>>>(Wq, Wk, Wv, Wo);

    hgemm_qkv<<<dim3(DD / 128, MTOT / 128, 3), 256, GSMEM>>>(queries, keys, values,
                                                             bq, bk, bv);

    fused_probe_csum1<<<PROBE_BLOCKS + BH * 16, 256>>>(index_sample);
    fused_topk_csum2<<<2 * BH, 256>>>();
    fused_attn_csum3<<<F3_ATTN_BLOCKS + BH * 16, 256, ATTN_SMEM>>>();

    hgemm_out<<<dim3(DD / 128, MTOT / 128, 1), 256, GSMEM>>>(bo, out);
}